// round 8
// baseline (speedup 1.0000x reference)
#include <cuda_runtime.h>
#include <cuda_fp16.h>
#include <math.h>

#define B_TOK 4096
#define D_DIM 9216
#define E_EXP 8
#define H_DIM 128
#define O_DIM 10
#define SPLITS 6
#define KCH (D_DIM / SPLITS)   // 1536

// ---------------- scratch (static device globals; no runtime allocation) ----
__device__ float g_h[(size_t)B_TOK * D_DIM];          // features [B, 9216]
__device__ float g_scale[B_TOK];                      // top-1 gate prob
__device__ int   g_bucket[E_EXP * B_TOK];             // token ids per expert
__device__ int   g_cnt[E_EXP];
__device__ float g_part[SPLITS][B_TOK][H_DIM];        // split-K partials

__global__ void reset_kernel() {
    if (threadIdx.x < E_EXP) g_cnt[threadIdx.x] = 0;
}

// ---------------- mma helper -------------------------------------------------
__device__ __forceinline__ void mma_f16(float c[4],
                                        unsigned a0, unsigned a1,
                                        unsigned a2, unsigned a3,
                                        unsigned b0, unsigned b1) {
    asm("mma.sync.aligned.m16n8k16.row.col.f32.f16.f16.f32 "
        "{%0,%1,%2,%3},{%4,%5,%6,%7},{%8,%9},{%0,%1,%2,%3};"
        : "+f"(c[0]), "+f"(c[1]), "+f"(c[2]), "+f"(c[3])
        : "r"(a0), "r"(a1), "r"(a2), "r"(a3), "r"(b0), "r"(b1));
}

__device__ __forceinline__ unsigned h2u(__half2 h) {
    return *reinterpret_cast<unsigned*>(&h);
}

// ---------------- fused conv1 -> conv2(fp16 3-term mma) -> maxpool -----------
// One block per image, 576 threads (18 warps), each warp owns 2 m-tiles.
// Exact-split fp16: aw = ah*wh + (al*64)*(w/64) + (ah/64)*(wl*64)
//   (covers ah*wh + al*w + ah*wl = aw; only residual-repr errors ~2e-7 remain)
// SMEM floats:
//   s_in[784] s_c1w[288] s_c1b[32] s_c2b[64] s_coff[288](int)
//   s_c1[21632]  conv1 relu acts (temp: raw c2w during B prep)
//   s_Bf          3 sets x 8 nt x 18 ks x 32 lanes of uint2 (packed B frags)
#define CONV_THREADS 576
#define NKS 18                         // 288 / 16
#define OFF_IN   0
#define OFF_C1W  784
#define OFF_C1B  1072
#define OFF_C2B  1104
#define OFF_COFF 1168
#define OFF_C1   1456
#define OFF_BF   (OFF_C1 + 21632)      // 23088 (x4B = 92352, 8B aligned)
#define BF_U2    (3 * 8 * NKS * 32)    // 13824 uint2
#define CONV_SMEM_FLOATS (OFF_BF + BF_U2 * 2)   // 50736 floats = 202944 B

__global__ __launch_bounds__(CONV_THREADS, 1)
void conv_kernel(const float* __restrict__ x,
                 const float* __restrict__ c1w, const float* __restrict__ c1b,
                 const float* __restrict__ c2w, const float* __restrict__ c2b) {
    extern __shared__ float sm[];
    float* s_in   = sm + OFF_IN;
    float* s_c1w  = sm + OFF_C1W;
    float* s_c1b  = sm + OFF_C1B;
    float* s_c2b  = sm + OFF_C2B;
    int*   s_coff = (int*)(sm + OFF_COFF);
    float* s_c1   = sm + OFF_C1;
    uint2* s_Bf   = (uint2*)(sm + OFF_BF);

    const int b = blockIdx.x;
    const int t = threadIdx.x;

    // ---- phase 0: stage inputs; raw c2w parked in s_c1 ---------------------
    const float* xin = x + b * 784;
    for (int i = t; i < 784; i += CONV_THREADS) s_in[i] = xin[i];
    for (int i = t; i < 288; i += CONV_THREADS) s_c1w[i] = c1w[i];
    if (t < 32) s_c1b[t] = c1b[t];
    if (t >= 64 && t < 128) s_c2b[t - 64] = c2b[t - 64];
    if (t >= 128 && t < 416) {
        int k = t - 128;
        int ic = k / 9, kk = k - ic * 9;
        s_coff[k] = ic * 676 + (kk / 3) * 26 + (kk % 3);
    }
    for (int i = t; i < 18432; i += CONV_THREADS) s_c1[i] = c2w[i]; // raw [oc][k]
    __syncthreads();

    // ---- phase 1: pack B fragments (3 fp16 sets) ---------------------------
    // slot(set,nt,ks,lane): lane(g=lane>>2,tg=lane&3) holds
    //   halves (k=16ks+2tg, +1) and (k+8, +9) for n = nt*8+g.
    for (int i = t; i < 8 * NKS * 32; i += CONV_THREADS) {
        int lane = i & 31;
        int rest = i >> 5;
        int ks = rest % NKS;
        int nt = rest / NKS;
        int tg = lane & 3, g = lane >> 2;
        int n = nt * 8 + g;
        int k0 = ks * 16 + 2 * tg;
        const float* wr = s_c1 + n * 288;
        float w0 = wr[k0],     w1 = wr[k0 + 1];
        float w8 = wr[k0 + 8], w9 = wr[k0 + 9];
        __half2 h0 = __floats2half2_rn(w0, w1);
        __half2 h1 = __floats2half2_rn(w8, w9);
        float2 r0 = __half22float2(h0);
        float2 r1 = __half22float2(h1);
        __half2 l0 = __floats2half2_rn((w0 - r0.x) * 64.f, (w1 - r0.y) * 64.f);
        __half2 l1 = __floats2half2_rn((w8 - r1.x) * 64.f, (w9 - r1.y) * 64.f);
        __half2 s0 = __floats2half2_rn(w0 * 0.015625f, w1 * 0.015625f);
        __half2 s1 = __floats2half2_rn(w8 * 0.015625f, w9 * 0.015625f);
        int slot = (nt * NKS + ks) * 32 + lane;
        s_Bf[slot]               = make_uint2(h2u(h0), h2u(h1));  // wh
        s_Bf[slot + 8 * NKS * 32] = make_uint2(h2u(s0), h2u(s1)); // w/64
        s_Bf[slot + 16 * NKS * 32] = make_uint2(h2u(l0), h2u(l1)); // wl*64
    }
    __syncthreads();

    // ---- phase 2: conv1 + relu (fp32) overwrites raw c2w -------------------
    for (int i = t; i < 21632; i += CONV_THREADS) {
        int c  = i / 676;
        int p  = i - c * 676;
        int y  = p / 26;
        int xx = p - y * 26;
        const float* wv = s_c1w + c * 9;
        const float* ip = s_in + y * 28 + xx;
        float acc = s_c1b[c];
        #pragma unroll
        for (int ky = 0; ky < 3; ky++)
            #pragma unroll
            for (int kx = 0; kx < 3; kx++)
                acc = fmaf(ip[ky * 28 + kx], wv[ky * 3 + kx], acc);
        s_c1[i] = fmaxf(acc, 0.f);
    }
    __syncthreads();

    // ---- phase 3: conv2 implicit GEMM, 3x fp16 mma, fused maxpool ----------
    const int lane = t & 31;
    const int wid  = t >> 5;             // 0..17
    const int g    = lane >> 2;          // 0..7
    const int tg   = lane & 3;           // 0..3

    float* hb = g_h + (size_t)b * D_DIM;
    const __half2 inv64 = __floats2half2_rn(0.015625f, 0.015625f);

    #pragma unroll
    for (int ti = 0; ti < 2; ti++) {
        const int tt = wid * 2 + ti;     // m-tile 0..35
        const int q  = tt * 4 + (g & 3); // pooled position 0..143
        const int p  = (q / 12) * 52 + (q % 12) * 2 + (g >> 2);
        const int p26 = p + 26;

        float acc[8][4];
        #pragma unroll
        for (int nt = 0; nt < 8; nt++)
            #pragma unroll
            for (int i = 0; i < 4; i++) acc[nt][i] = 0.f;

        for (int ks = 0; ks < NKS; ks++) {
            const int kb = ks * 16 + 2 * tg;
            const int c0 = s_coff[kb],     c1 = s_coff[kb + 1];
            const int c2 = s_coff[kb + 8], c3 = s_coff[kb + 9];

            float f00 = s_c1[p + c0],   f01 = s_c1[p + c1];
            float f02 = s_c1[p + c2],   f03 = s_c1[p + c3];
            float f10 = s_c1[p26 + c0], f11 = s_c1[p26 + c1];
            float f12 = s_c1[p26 + c2], f13 = s_c1[p26 + c3];

            // hi (fp16), residual*64 (fp16), hi/64 (fp16)
            __half2 ah0 = __floats2half2_rn(f00, f01);
            __half2 ah1 = __floats2half2_rn(f10, f11);
            __half2 ah2 = __floats2half2_rn(f02, f03);
            __half2 ah3 = __floats2half2_rn(f12, f13);
            float2 r0 = __half22float2(ah0), r1 = __half22float2(ah1);
            float2 r2 = __half22float2(ah2), r3 = __half22float2(ah3);
            __half2 al0 = __floats2half2_rn((f00 - r0.x) * 64.f, (f01 - r0.y) * 64.f);
            __half2 al1 = __floats2half2_rn((f10 - r1.x) * 64.f, (f11 - r1.y) * 64.f);
            __half2 al2 = __floats2half2_rn((f02 - r2.x) * 64.f, (f03 - r2.y) * 64.f);
            __half2 al3 = __floats2half2_rn((f12 - r3.x) * 64.f, (f13 - r3.y) * 64.f);
            __half2 as0 = __hmul2(ah0, inv64);
            __half2 as1 = __hmul2(ah1, inv64);
            __half2 as2 = __hmul2(ah2, inv64);
            __half2 as3 = __hmul2(ah3, inv64);

            unsigned uh0 = h2u(ah0), uh1 = h2u(ah1), uh2 = h2u(ah2), uh3 = h2u(ah3);
            unsigned ul0 = h2u(al0), ul1 = h2u(al1), ul2 = h2u(al2), ul3 = h2u(al3);
            unsigned us0 = h2u(as0), us1 = h2u(as1), us2 = h2u(as2), us3 = h2u(as3);

            const uint2* bp = s_Bf + ks * 32 + lane;
            #pragma unroll
            for (int nt = 0; nt < 8; nt++) {
                uint2 bwh = bp[nt * (NKS * 32)];                  // wh
                uint2 bws = bp[nt * (NKS * 32) + 8 * NKS * 32];   // w/64
                uint2 bwl = bp[nt * (NKS * 32) + 16 * NKS * 32];  // wl*64
                mma_f16(acc[nt], uh0, uh1, uh2, uh3, bwh.x, bwh.y); // ah*wh
                mma_f16(acc[nt], ul0, ul1, ul2, ul3, bws.x, bws.y); // al*w
                mma_f16(acc[nt], us0, us1, us2, us3, bwl.x, bwl.y); // ah*wl
            }
        }

        // epilogue: maxpool (c-frag rows g,g+8 then shfl_xor 16), bias, relu
        #pragma unroll
        for (int nt = 0; nt < 8; nt++) {
            float v0 = fmaxf(acc[nt][0], acc[nt][2]);
            float v1 = fmaxf(acc[nt][1], acc[nt][3]);
            v0 = fmaxf(v0, __shfl_xor_sync(0xFFFFFFFFu, v0, 16));
            v1 = fmaxf(v1, __shfl_xor_sync(0xFFFFFFFFu, v1, 16));
            int ch0 = nt * 8 + 2 * tg;
            if ((lane < 16) == (nt < 4)) {
                hb[ch0 * 144 + q]       = fmaxf(v0 + s_c2b[ch0], 0.f);
                hb[(ch0 + 1) * 144 + q] = fmaxf(v1 + s_c2b[ch0 + 1], 0.f);
            }
        }
    }
}

// ---------------- top-1 gate (vectorized): logits, prob, bucket build -------
__global__ __launch_bounds__(256)
void gate_kernel(const float* __restrict__ gate_w) {
    const int b = blockIdx.x;
    const int t = threadIdx.x;
    const float4* h4 = (const float4*)(g_h + (size_t)b * D_DIM);
    float acc[8];
    #pragma unroll
    for (int e = 0; e < 8; e++) acc[e] = 0.f;

    #pragma unroll
    for (int it = 0; it < 9; it++) {           // 9*256 = 2304 float4 = 9216
        int d4 = it * 256 + t;
        float4 hv = h4[d4];
        const float4* gp = (const float4*)(gate_w + (size_t)d4 * 32);
        float4 g0 = gp[0], g1 = gp[1];
        float4 g2 = gp[2], g3 = gp[3];
        float4 g4 = gp[4], g5 = gp[5];
        float4 g6 = gp[6], g7 = gp[7];
        acc[0] = fmaf(hv.x, g0.x, acc[0]); acc[1] = fmaf(hv.x, g0.y, acc[1]);
        acc[2] = fmaf(hv.x, g0.z, acc[2]); acc[3] = fmaf(hv.x, g0.w, acc[3]);
        acc[4] = fmaf(hv.x, g1.x, acc[4]); acc[5] = fmaf(hv.x, g1.y, acc[5]);
        acc[6] = fmaf(hv.x, g1.z, acc[6]); acc[7] = fmaf(hv.x, g1.w, acc[7]);
        acc[0] = fmaf(hv.y, g2.x, acc[0]); acc[1] = fmaf(hv.y, g2.y, acc[1]);
        acc[2] = fmaf(hv.y, g2.z, acc[2]); acc[3] = fmaf(hv.y, g2.w, acc[3]);
        acc[4] = fmaf(hv.y, g3.x, acc[4]); acc[5] = fmaf(hv.y, g3.y, acc[5]);
        acc[6] = fmaf(hv.y, g3.z, acc[6]); acc[7] = fmaf(hv.y, g3.w, acc[7]);
        acc[0] = fmaf(hv.z, g4.x, acc[0]); acc[1] = fmaf(hv.z, g4.y, acc[1]);
        acc[2] = fmaf(hv.z, g4.z, acc[2]); acc[3] = fmaf(hv.z, g4.w, acc[3]);
        acc[4] = fmaf(hv.z, g5.x, acc[4]); acc[5] = fmaf(hv.z, g5.y, acc[5]);
        acc[6] = fmaf(hv.z, g5.z, acc[6]); acc[7] = fmaf(hv.z, g5.w, acc[7]);
        acc[0] = fmaf(hv.w, g6.x, acc[0]); acc[1] = fmaf(hv.w, g6.y, acc[1]);
        acc[2] = fmaf(hv.w, g6.z, acc[2]); acc[3] = fmaf(hv.w, g6.w, acc[3]);
        acc[4] = fmaf(hv.w, g7.x, acc[4]); acc[5] = fmaf(hv.w, g7.y, acc[5]);
        acc[6] = fmaf(hv.w, g7.z, acc[6]); acc[7] = fmaf(hv.w, g7.w, acc[7]);
    }
    #pragma unroll
    for (int e = 0; e < 8; e++)
        #pragma unroll
        for (int off = 16; off > 0; off >>= 1)
            acc[e] += __shfl_down_sync(0xFFFFFFFFu, acc[e], off);

    __shared__ float red[8][8];
    int w = t >> 5, l = t & 31;
    if (l == 0) {
        #pragma unroll
        for (int e = 0; e < 8; e++) red[w][e] = acc[e];
    }
    __syncthreads();
    if (t == 0) {
        float lg[8];
        #pragma unroll
        for (int e = 0; e < 8; e++) {
            float s = 0.f;
            #pragma unroll
            for (int ww = 0; ww < 8; ww++) s += red[ww][e];
            lg[e] = s;
        }
        float m = lg[0];
        int idx = 0;
        #pragma unroll
        for (int e = 1; e < 8; e++) if (lg[e] > m) { m = lg[e]; idx = e; }
        float s = 0.f;
        #pragma unroll
        for (int e = 0; e < 8; e++) s += expf(lg[e] - m);
        g_scale[b] = 1.f / s;
        int pos = atomicAdd(&g_cnt[idx], 1);
        g_bucket[idx * B_TOK + pos] = b;
    }
}

// ---------------- ffn stage 1: split-K partial GEMM h @ w1 ------------------
__global__ __launch_bounds__(256)
void ffn1_kernel(const float* __restrict__ w1) {
    __shared__ float A_s[32 * 32];
    __shared__ float B_s[32 * 128];
    __shared__ int   tok_s[32];

    const int e  = blockIdx.y;
    const int mt = blockIdx.x;
    const int sp = blockIdx.z;
    const int t  = threadIdx.x;
    const int count = g_cnt[e];
    if (mt * 32 >= count) return;

    if (t < 32) {
        int r = mt * 32 + t;
        tok_s[t] = (r < count) ? g_bucket[e * B_TOK + r] : -1;
    }
    __syncthreads();

    const int row = t & 31;
    const int kg  = t >> 5;
    const int tx  = t & 31;
    const int ty  = t >> 5;

    int mytok = tok_s[row];
    const float* hrow = g_h + (size_t)(mytok >= 0 ? mytok : 0) * D_DIM
                        + sp * KCH + kg * 4;
    const float* w1e  = w1 + (size_t)e * D_DIM * H_DIM + (size_t)sp * KCH * H_DIM;

    float c[4][4];
    #pragma unroll
    for (int i = 0; i < 4; i++)
        #pragma unroll
        for (int jj = 0; jj < 4; jj++) c[i][jj] = 0.f;

    for (int k0 = 0; k0 < KCH; k0 += 32) {
        float4 av = *(const float4*)(hrow + k0);
        float4 bv[4];
        #pragma unroll
        for (int v = 0; v < 4; v++) {
            int i4 = t + 256 * v;
            int kk = i4 >> 5;
            int n4 = (i4 & 31) << 2;
            bv[v] = *(const float4*)(w1e + (size_t)(k0 + kk) * 128 + n4);
        }
        __syncthreads();
        A_s[(kg * 4 + 0) * 32 + row] = av.x;
        A_s[(kg * 4 + 1) * 32 + row] = av.y;
        A_s[(kg * 4 + 2) * 32 + row] = av.z;
        A_s[(kg * 4 + 3) * 32 + row] = av.w;
        #pragma unroll
        for (int v = 0; v < 4; v++) {
            int i4 = t + 256 * v;
            int kk = i4 >> 5;
            int n4 = (i4 & 31) << 2;
            *(float4*)(B_s + kk * 128 + n4) = bv[v];
        }
        __syncthreads();
        #pragma unroll
        for (int kk = 0; kk < 32; kk++) {
            float4 a = *(const float4*)(A_s + kk * 32 + ty * 4);
            float b0 = B_s[kk * 128 + tx];
            float bb1 = B_s[kk * 128 + tx + 32];
            float bb2 = B_s[kk * 128 + tx + 64];
            float bb3 = B_s[kk * 128 + tx + 96];
            c[0][0] = fmaf(a.x, b0, c[0][0]); c[0][1] = fmaf(a.x, bb1, c[0][1]);
            c[0][2] = fmaf(a.x, bb2, c[0][2]); c[0][3] = fmaf(a.x, bb3, c[0][3]);
            c[1][0] = fmaf(a.y, b0, c[1][0]); c[1][1] = fmaf(a.y, bb1, c[1][1]);
            c[1][2] = fmaf(a.y, bb2, c[1][2]); c[1][3] = fmaf(a.y, bb3, c[1][3]);
            c[2][0] = fmaf(a.z, b0, c[2][0]); c[2][1] = fmaf(a.z, bb1, c[2][1]);
            c[2][2] = fmaf(a.z, bb2, c[2][2]); c[2][3] = fmaf(a.z, bb3, c[2][3]);
            c[3][0] = fmaf(a.w, b0, c[3][0]); c[3][1] = fmaf(a.w, bb1, c[3][1]);
            c[3][2] = fmaf(a.w, bb2, c[3][2]); c[3][3] = fmaf(a.w, bb3, c[3][3]);
        }
    }

    #pragma unroll
    for (int i = 0; i < 4; i++) {
        int rr = ty * 4 + i;
        int tok = tok_s[rr];
        if (tok >= 0) {
            float* pr = &g_part[sp][tok][0];
            pr[tx]      = c[i][0];
            pr[tx + 32] = c[i][1];
            pr[tx + 64] = c[i][2];
            pr[tx + 96] = c[i][3];
        }
    }
}

// ---------------- ffn stage 2: reduce + b1 + relu + w2 + log_softmax --------
__global__ __launch_bounds__(256)
void ffn2_kernel(const float* __restrict__ b1, const float* __restrict__ w2,
                 const float* __restrict__ b2, float* __restrict__ out) {
    __shared__ float he_s[32 * 129];
    __shared__ int   tok_s[32];

    const int e  = blockIdx.y;
    const int mt = blockIdx.x;
    const int t  = threadIdx.x;
    const int count = g_cnt[e];
    if (mt * 32 >= count) return;

    if (t < 32) {
        int r = mt * 32 + t;
        tok_s[t] = (r < count) ? g_bucket[e * B_TOK + r] : -1;
    }
    __syncthreads();

    const float* b1e = b1 + e * H_DIM;
    for (int i4 = t; i4 < 1024; i4 += 256) {
        int row = i4 >> 5;
        int c4  = (i4 & 31) << 2;
        int tok = tok_s[row];
        float sx = 0.f, sy = 0.f, sz = 0.f, sw = 0.f;
        if (tok >= 0) {
            #pragma unroll
            for (int sp = 0; sp < SPLITS; sp++) {
                float4 p = *(const float4*)&g_part[sp][tok][c4];
                sx += p.x; sy += p.y; sz += p.z; sw += p.w;
            }
        }
        he_s[row * 129 + c4 + 0] = fmaxf(sx + b1e[c4 + 0], 0.f);
        he_s[row * 129 + c4 + 1] = fmaxf(sy + b1e[c4 + 1], 0.f);
        he_s[row * 129 + c4 + 2] = fmaxf(sz + b1e[c4 + 2], 0.f);
        he_s[row * 129 + c4 + 3] = fmaxf(sw + b1e[c4 + 3], 0.f);
    }
    __syncthreads();

    if (t < 32) {
        int r = mt * 32 + t;
        if (r < count) {
            int tok = tok_s[t];
            const float* w2e = w2 + e * (H_DIM * O_DIM);
            const float* b2e = b2 + e * O_DIM;
            float o[O_DIM];
            #pragma unroll
            for (int oo = 0; oo < O_DIM; oo++) o[oo] = b2e[oo];
            const float* hh = he_s + t * 129;
            for (int hi = 0; hi < H_DIM; hi++) {
                float hv = hh[hi];
                const float* wr = w2e + hi * O_DIM;
                #pragma unroll
                for (int oo = 0; oo < O_DIM; oo++)
                    o[oo] = fmaf(hv, wr[oo], o[oo]);
            }
            float sc = g_scale[tok];
            float m = -1e30f;
            #pragma unroll
            for (int oo = 0; oo < O_DIM; oo++) { o[oo] *= sc; m = fmaxf(m, o[oo]); }
            float s = 0.f;
            #pragma unroll
            for (int oo = 0; oo < O_DIM; oo++) s += expf(o[oo] - m);
            float lse = m + logf(s);
            #pragma unroll
            for (int oo = 0; oo < O_DIM; oo++)
                out[tok * O_DIM + oo] = o[oo] - lse;
        }
    }
}

// ---------------- launch ----------------------------------------------------
extern "C" void kernel_launch(void* const* d_in, const int* in_sizes, int n_in,
                              void* d_out, int out_size) {
    const float* x    = (const float*)d_in[0];
    const float* c1w  = (const float*)d_in[1];
    const float* c1b  = (const float*)d_in[2];
    const float* c2w  = (const float*)d_in[3];
    const float* c2b  = (const float*)d_in[4];
    const float* gw   = (const float*)d_in[5];
    const float* w1   = (const float*)d_in[6];
    const float* b1   = (const float*)d_in[7];
    const float* w2   = (const float*)d_in[8];
    const float* b2   = (const float*)d_in[9];
    float* out = (float*)d_out;

    cudaFuncSetAttribute(conv_kernel, cudaFuncAttributeMaxDynamicSharedMemorySize,
                         CONV_SMEM_FLOATS * (int)sizeof(float));

    reset_kernel<<<1, 32>>>();
    conv_kernel<<<B_TOK, CONV_THREADS, CONV_SMEM_FLOATS * sizeof(float)>>>(
        x, c1w, c1b, c2w, c2b);
    gate_kernel<<<B_TOK, 256>>>(gw);
    ffn1_kernel<<<dim3(128, E_EXP, SPLITS), 256>>>(w1);
    ffn2_kernel<<<dim3(128, E_EXP), 256>>>(b1, w2, b2, out);
}

// round 11
// speedup vs baseline: 1.1199x; 1.1199x over previous
#include <cuda_runtime.h>
#include <cuda_fp16.h>
#include <math.h>

#define B_TOK 4096
#define D_DIM 9216
#define E_EXP 8
#define H_DIM 128
#define O_DIM 10
#define SPLITS 6
#define KCH (D_DIM / SPLITS)   // 1536

// ---------------- scratch (static device globals) ----------------------------
__device__ unsigned g_hp[(size_t)B_TOK * D_DIM];      // h packed (hi, lo*2048)
__device__ float    g_scale[B_TOK];
__device__ int      g_bucket[E_EXP * B_TOK];
__device__ int      g_cnt[E_EXP];
__device__ float    g_part[SPLITS][B_TOK][H_DIM];
__device__ unsigned g_w1h[(size_t)E_EXP * 4608 * 128]; // w1 fp16 k-pairs

__global__ void reset_kernel() {
    if (threadIdx.x < E_EXP) g_cnt[threadIdx.x] = 0;
}

// ---------------- helpers ----------------------------------------------------
__device__ __forceinline__ void mma_f16(float c[4],
                                        unsigned a0, unsigned a1,
                                        unsigned a2, unsigned a3,
                                        unsigned b0, unsigned b1) {
    asm("mma.sync.aligned.m16n8k16.row.col.f32.f16.f16.f32 "
        "{%0,%1,%2,%3},{%4,%5,%6,%7},{%8,%9},{%0,%1,%2,%3};"
        : "+f"(c[0]), "+f"(c[1]), "+f"(c[2]), "+f"(c[3])
        : "r"(a0), "r"(a1), "r"(a2), "r"(a3), "r"(b0), "r"(b1));
}
__device__ __forceinline__ unsigned h2u(__half2 h) { return *reinterpret_cast<unsigned*>(&h); }
__device__ __forceinline__ __half2 u2h(unsigned u) { return *reinterpret_cast<__half2*>(&u); }
__device__ __forceinline__ float unpackh(unsigned u) {
    return __half2float(__ushort_as_half((unsigned short)(u & 0xffff)))
         + __half2float(__ushort_as_half((unsigned short)(u >> 16))) * 4.8828125e-4f;
}
__device__ __forceinline__ unsigned packh(float v) {
    __half hi = __float2half_rn(v);
    __half lo = __float2half_rn((v - __half2float(hi)) * 2048.f);
    return ((unsigned)__half_as_ushort(lo) << 16) | (unsigned)__half_as_ushort(hi);
}

// ---------------- w1 -> fp16 k-pair pack -------------------------------------
__global__ __launch_bounds__(256)
void w1pack_kernel(const float* __restrict__ w1) {
    size_t idx = (size_t)blockIdx.x * 256 + threadIdx.x;   // E*4608*128
    int n   = (int)(idx & 127);
    int row = (int)(idx >> 7);          // 0..36863
    int e   = row / 4608;
    int kp  = row - e * 4608;
    const float* we = w1 + (size_t)e * D_DIM * H_DIM;
    float w0 = we[(size_t)(2 * kp) * 128 + n];
    float w1v = we[(size_t)(2 * kp + 1) * 128 + n];
    g_w1h[idx] = h2u(__floats2half2_rn(w0, w1v));
}

// ---------------- fused conv1 -> conv2(fp16 3-term mma) -> maxpool -----------
#define CONV_THREADS 576
#define NKS 18
#define OFF_IN   0
#define OFF_C1W  784
#define OFF_C1B  1072
#define OFF_C2B  1104
#define OFF_COFF 1168
#define OFF_C1   1456
#define OFF_BF   (OFF_C1 + 21632)
#define BF_U2    (3 * 8 * NKS * 32)
#define CONV_SMEM_FLOATS (OFF_BF + BF_U2 * 2)

__global__ __launch_bounds__(CONV_THREADS, 1)
void conv_kernel(const float* __restrict__ x,
                 const float* __restrict__ c1w, const float* __restrict__ c1b,
                 const float* __restrict__ c2w, const float* __restrict__ c2b) {
    extern __shared__ float sm[];
    float*    s_in   = sm + OFF_IN;
    float*    s_c1w  = sm + OFF_C1W;
    float*    s_c1b  = sm + OFF_C1B;
    float*    s_c2b  = sm + OFF_C2B;
    int*      s_coff = (int*)(sm + OFF_COFF);
    float*    s_c1   = sm + OFF_C1;            // fp32 view (parked c2w)
    unsigned* s_c1p  = (unsigned*)(sm + OFF_C1); // u32 view (packed acts)
    uint2*    s_Bf   = (uint2*)(sm + OFF_BF);

    const int b = blockIdx.x;
    const int t = threadIdx.x;

    // phase 0: stage inputs; raw c2w parked in s_c1
    const float* xin = x + b * 784;
    for (int i = t; i < 784; i += CONV_THREADS) s_in[i] = xin[i];
    for (int i = t; i < 288; i += CONV_THREADS) s_c1w[i] = c1w[i];
    if (t < 32) s_c1b[t] = c1b[t];
    if (t >= 64 && t < 128) s_c2b[t - 64] = c2b[t - 64];
    if (t >= 128 && t < 416) {
        int k = t - 128;
        int ic = k / 9, kk = k - ic * 9;
        s_coff[k] = ic * 676 + (kk / 3) * 26 + (kk % 3);
    }
    for (int i = t; i < 18432; i += CONV_THREADS) s_c1[i] = c2w[i];
    __syncthreads();

    // phase 1: pack B fragments (wh, w/64, wl*64)
    for (int i = t; i < 8 * NKS * 32; i += CONV_THREADS) {
        int lane = i & 31;
        int rest = i >> 5;
        int ks = rest % NKS;
        int nt = rest / NKS;
        int tg = lane & 3, g = lane >> 2;
        int n = nt * 8 + g;
        int k0 = ks * 16 + 2 * tg;
        const float* wr = s_c1 + n * 288;
        float w0 = wr[k0],     w1 = wr[k0 + 1];
        float w8 = wr[k0 + 8], w9 = wr[k0 + 9];
        __half2 h0 = __floats2half2_rn(w0, w1);
        __half2 h1 = __floats2half2_rn(w8, w9);
        float2 r0 = __half22float2(h0);
        float2 r1 = __half22float2(h1);
        __half2 l0 = __floats2half2_rn((w0 - r0.x) * 64.f, (w1 - r0.y) * 64.f);
        __half2 l1 = __floats2half2_rn((w8 - r1.x) * 64.f, (w9 - r1.y) * 64.f);
        __half2 s0 = __floats2half2_rn(w0 * 0.015625f, w1 * 0.015625f);
        __half2 s1 = __floats2half2_rn(w8 * 0.015625f, w9 * 0.015625f);
        int slot = (nt * NKS + ks) * 32 + lane;
        s_Bf[slot]                 = make_uint2(h2u(h0), h2u(h1));
        s_Bf[slot + 8 * NKS * 32]  = make_uint2(h2u(s0), h2u(s1));
        s_Bf[slot + 16 * NKS * 32] = make_uint2(h2u(l0), h2u(l1));
    }
    __syncthreads();

    // phase 2: conv1 + relu, packed (hi, lo*2048)
    for (int i = t; i < 21632; i += CONV_THREADS) {
        int c  = i / 676;
        int p  = i - c * 676;
        int y  = p / 26;
        int xx = p - y * 26;
        const float* wv = s_c1w + c * 9;
        const float* ip = s_in + y * 28 + xx;
        float acc = s_c1b[c];
        #pragma unroll
        for (int ky = 0; ky < 3; ky++)
            #pragma unroll
            for (int kx = 0; kx < 3; kx++)
                acc = fmaf(ip[ky * 28 + kx], wv[ky * 3 + kx], acc);
        s_c1p[i] = packh(fmaxf(acc, 0.f));
    }
    __syncthreads();

    // phase 3: implicit GEMM, 3x fp16 mma, A from packed acts (prmt path)
    const int lane = t & 31;
    const int wid  = t >> 5;
    const int g    = lane >> 2;
    const int tg   = lane & 3;
    unsigned* hbp = g_hp + (size_t)b * D_DIM;
    const __half2 k5 = __floats2half2_rn(0.03125f, 0.03125f);     // 2^-5
    const __half2 k6 = __floats2half2_rn(0.015625f, 0.015625f);   // 2^-6

    #pragma unroll
    for (int ti = 0; ti < 2; ti++) {
        const int tt = wid * 2 + ti;
        const int q  = tt * 4 + (g & 3);
        const int p  = (q / 12) * 52 + (q % 12) * 2 + (g >> 2);
        const int p26 = p + 26;

        float acc[8][4];
        #pragma unroll
        for (int nt = 0; nt < 8; nt++)
            #pragma unroll
            for (int i = 0; i < 4; i++) acc[nt][i] = 0.f;

        for (int ks = 0; ks < NKS; ks++) {
            const int kb = ks * 16 + 2 * tg;
            const int c0 = s_coff[kb],     c1 = s_coff[kb + 1];
            const int c2 = s_coff[kb + 8], c3 = s_coff[kb + 9];
            unsigned u00 = s_c1p[p + c0],   u01 = s_c1p[p + c1];
            unsigned u02 = s_c1p[p + c2],   u03 = s_c1p[p + c3];
            unsigned u10 = s_c1p[p26 + c0], u11 = s_c1p[p26 + c1];
            unsigned u12 = s_c1p[p26 + c2], u13 = s_c1p[p26 + c3];

            unsigned ah0 = __byte_perm(u00, u01, 0x5410);
            unsigned ah1 = __byte_perm(u10, u11, 0x5410);
            unsigned ah2 = __byte_perm(u02, u03, 0x5410);
            unsigned ah3 = __byte_perm(u12, u13, 0x5410);
            unsigned al0 = h2u(__hmul2(u2h(__byte_perm(u00, u01, 0x7632)), k5));
            unsigned al1 = h2u(__hmul2(u2h(__byte_perm(u10, u11, 0x7632)), k5));
            unsigned al2 = h2u(__hmul2(u2h(__byte_perm(u02, u03, 0x7632)), k5));
            unsigned al3 = h2u(__hmul2(u2h(__byte_perm(u12, u13, 0x7632)), k5));
            unsigned us0 = h2u(__hmul2(u2h(ah0), k6));
            unsigned us1 = h2u(__hmul2(u2h(ah1), k6));
            unsigned us2 = h2u(__hmul2(u2h(ah2), k6));
            unsigned us3 = h2u(__hmul2(u2h(ah3), k6));

            const uint2* bp = s_Bf + ks * 32 + lane;
            #pragma unroll
            for (int nt = 0; nt < 8; nt++) {
                uint2 bwh = bp[nt * (NKS * 32)];
                uint2 bws = bp[nt * (NKS * 32) + 8 * NKS * 32];
                uint2 bwl = bp[nt * (NKS * 32) + 16 * NKS * 32];
                mma_f16(acc[nt], ah0, ah1, ah2, ah3, bwh.x, bwh.y); // ah*wh
                mma_f16(acc[nt], al0, al1, al2, al3, bws.x, bws.y); // (al*64)*(w/64)
                mma_f16(acc[nt], us0, us1, us2, us3, bwl.x, bwl.y); // (ah/64)*(wl*64)
            }
        }

        #pragma unroll
        for (int nt = 0; nt < 8; nt++) {
            float v0 = fmaxf(acc[nt][0], acc[nt][2]);
            float v1 = fmaxf(acc[nt][1], acc[nt][3]);
            v0 = fmaxf(v0, __shfl_xor_sync(0xFFFFFFFFu, v0, 16));
            v1 = fmaxf(v1, __shfl_xor_sync(0xFFFFFFFFu, v1, 16));
            int ch0 = nt * 8 + 2 * tg;
            if ((lane < 16) == (nt < 4)) {
                hbp[ch0 * 144 + q]       = packh(fmaxf(v0 + s_c2b[ch0], 0.f));
                hbp[(ch0 + 1) * 144 + q] = packh(fmaxf(v1 + s_c2b[ch0 + 1], 0.f));
            }
        }
    }
}

// ---------------- top-1 gate (packed h) --------------------------------------
__global__ __launch_bounds__(256)
void gate_kernel(const float* __restrict__ gate_w) {
    const int b = blockIdx.x, t = threadIdx.x;
    const uint4* h4 = (const uint4*)(g_hp + (size_t)b * D_DIM);
    float acc[8];
    #pragma unroll
    for (int e = 0; e < 8; e++) acc[e] = 0.f;
    #pragma unroll
    for (int it = 0; it < 9; it++) {
        int d4 = it * 256 + t;
        uint4 hp = h4[d4];
        float hx = unpackh(hp.x), hy = unpackh(hp.y);
        float hz = unpackh(hp.z), hw = unpackh(hp.w);
        const float4* gp = (const float4*)(gate_w + (size_t)d4 * 32);
        float4 g0 = gp[0], g1 = gp[1], g2 = gp[2], g3 = gp[3];
        float4 g4 = gp[4], g5 = gp[5], g6 = gp[6], g7 = gp[7];
        acc[0] = fmaf(hx, g0.x, acc[0]); acc[1] = fmaf(hx, g0.y, acc[1]);
        acc[2] = fmaf(hx, g0.z, acc[2]); acc[3] = fmaf(hx, g0.w, acc[3]);
        acc[4] = fmaf(hx, g1.x, acc[4]); acc[5] = fmaf(hx, g1.y, acc[5]);
        acc[6] = fmaf(hx, g1.z, acc[6]); acc[7] = fmaf(hx, g1.w, acc[7]);
        acc[0] = fmaf(hy, g2.x, acc[0]); acc[1] = fmaf(hy, g2.y, acc[1]);
        acc[2] = fmaf(hy, g2.z, acc[2]); acc[3] = fmaf(hy, g2.w, acc[3]);
        acc[4] = fmaf(hy, g3.x, acc[4]); acc[5] = fmaf(hy, g3.y, acc[5]);
        acc[6] = fmaf(hy, g3.z, acc[6]); acc[7] = fmaf(hy, g3.w, acc[7]);
        acc[0] = fmaf(hz, g4.x, acc[0]); acc[1] = fmaf(hz, g4.y, acc[1]);
        acc[2] = fmaf(hz, g4.z, acc[2]); acc[3] = fmaf(hz, g4.w, acc[3]);
        acc[4] = fmaf(hz, g5.x, acc[4]); acc[5] = fmaf(hz, g5.y, acc[5]);
        acc[6] = fmaf(hz, g5.z, acc[6]); acc[7] = fmaf(hz, g5.w, acc[7]);
        acc[0] = fmaf(hw, g6.x, acc[0]); acc[1] = fmaf(hw, g6.y, acc[1]);
        acc[2] = fmaf(hw, g6.z, acc[2]); acc[3] = fmaf(hw, g6.w, acc[3]);
        acc[4] = fmaf(hw, g7.x, acc[4]); acc[5] = fmaf(hw, g7.y, acc[5]);
        acc[6] = fmaf(hw, g7.z, acc[6]); acc[7] = fmaf(hw, g7.w, acc[7]);
    }
    #pragma unroll
    for (int e = 0; e < 8; e++)
        #pragma unroll
        for (int off = 16; off > 0; off >>= 1)
            acc[e] += __shfl_down_sync(0xFFFFFFFFu, acc[e], off);
    __shared__ float red[8][8];
    int w = t >> 5, l = t & 31;
    if (l == 0)
        #pragma unroll
        for (int e = 0; e < 8; e++) red[w][e] = acc[e];
    __syncthreads();
    if (t == 0) {
        float lg[8];
        #pragma unroll
        for (int e = 0; e < 8; e++) {
            float s = 0.f;
            #pragma unroll
            for (int ww = 0; ww < 8; ww++) s += red[ww][e];
            lg[e] = s;
        }
        float m = lg[0];
        int idx = 0;
        #pragma unroll
        for (int e = 1; e < 8; e++) if (lg[e] > m) { m = lg[e]; idx = e; }
        float s = 0.f;
        #pragma unroll
        for (int e = 0; e < 8; e++) s += expf(lg[e] - m);
        g_scale[b] = 1.f / s;
        int pos = atomicAdd(&g_cnt[idx], 1);
        g_bucket[idx * B_TOK + pos] = b;
    }
}

// ---------------- ffn stage 1: fp16 2-term tensor GEMM -----------------------
// grid (128 mt, 8 e, 6 sp), 256 thr. M=32 tok, N=128, K=KCH (stage 64).
__global__ __launch_bounds__(256)
void ffn1_kernel() {
    __shared__ unsigned A_s[64 * 34];    // [k][tok], stride 34
    __shared__ unsigned B_s[32 * 132];   // [kpair][n], stride 132
    __shared__ int tok_s[32];

    const int e = blockIdx.y, mt = blockIdx.x, sp = blockIdx.z, t = threadIdx.x;
    const int count = g_cnt[e];
    if (mt * 32 >= count) return;
    if (t < 32) {
        int r = mt * 32 + t;
        tok_s[t] = (r < count) ? g_bucket[e * B_TOK + r] : -1;
    }
    __syncthreads();

    const int lane = t & 31, w = t >> 5;
    const int g = lane >> 2, tg = lane & 3;
    const int mt2 = w & 1;                 // m16 tile
    const int nb  = (w >> 1) * 32;         // n base (4 n8-tiles)
    const int tokA = mt2 * 16 + g;
    const __half2 k11 = __floats2half2_rn(4.8828125e-4f, 4.8828125e-4f); // 2^-11

    float acc[4][4];
    #pragma unroll
    for (int nt = 0; nt < 4; nt++)
        #pragma unroll
        for (int i = 0; i < 4; i++) acc[nt][i] = 0.f;

    const int rowbase = e * 4608 + sp * 768;

    for (int kb = 0; kb < KCH; kb += 64) {
        unsigned uA[8];
        uint4 uB[4];
        #pragma unroll
        for (int v = 0; v < 8; v++) {
            int i = t + 256 * v;
            int ltok = i >> 6, lk = i & 63;
            int tk = tok_s[ltok];
            uA[v] = g_hp[(size_t)(tk >= 0 ? tk : 0) * D_DIM + sp * KCH + kb + lk];
        }
        #pragma unroll
        for (int v = 0; v < 4; v++) {
            int f = t + 256 * v;
            int kp = f >> 5, n4 = (f & 31) * 4;
            uB[v] = *(const uint4*)&g_w1h[(size_t)(rowbase + (kb >> 1) + kp) * 128 + n4];
        }
        __syncthreads();
        #pragma unroll
        for (int v = 0; v < 8; v++) {
            int i = t + 256 * v;
            A_s[(i & 63) * 34 + (i >> 6)] = uA[v];
        }
        #pragma unroll
        for (int v = 0; v < 4; v++) {
            int f = t + 256 * v;
            int kp = f >> 5, n4 = (f & 31) * 4;
            *(uint4*)&B_s[kp * 132 + n4] = uB[v];
        }
        __syncthreads();

        #pragma unroll
        for (int s = 0; s < 4; s++) {
            const int K = s * 16;
            unsigned u00 = A_s[(K + 2 * tg) * 34 + tokA];
            unsigned u01 = A_s[(K + 2 * tg + 1) * 34 + tokA];
            unsigned u02 = A_s[(K + 2 * tg + 8) * 34 + tokA];
            unsigned u03 = A_s[(K + 2 * tg + 9) * 34 + tokA];
            unsigned u10 = A_s[(K + 2 * tg) * 34 + tokA + 8];
            unsigned u11 = A_s[(K + 2 * tg + 1) * 34 + tokA + 8];
            unsigned u12 = A_s[(K + 2 * tg + 8) * 34 + tokA + 8];
            unsigned u13 = A_s[(K + 2 * tg + 9) * 34 + tokA + 8];
            unsigned ah0 = __byte_perm(u00, u01, 0x5410);
            unsigned ah1 = __byte_perm(u10, u11, 0x5410);
            unsigned ah2 = __byte_perm(u02, u03, 0x5410);
            unsigned ah3 = __byte_perm(u12, u13, 0x5410);
            unsigned al0 = h2u(__hmul2(u2h(__byte_perm(u00, u01, 0x7632)), k11));
            unsigned al1 = h2u(__hmul2(u2h(__byte_perm(u10, u11, 0x7632)), k11));
            unsigned al2 = h2u(__hmul2(u2h(__byte_perm(u02, u03, 0x7632)), k11));
            unsigned al3 = h2u(__hmul2(u2h(__byte_perm(u12, u13, 0x7632)), k11));
            const int kq = s * 8;
            #pragma unroll
            for (int nt = 0; nt < 4; nt++) {
                int n = nb + nt * 8 + g;
                unsigned b0 = B_s[(kq + tg) * 132 + n];
                unsigned b1 = B_s[(kq + tg + 4) * 132 + n];
                mma_f16(acc[nt], ah0, ah1, ah2, ah3, b0, b1);
                mma_f16(acc[nt], al0, al1, al2, al3, b0, b1);
            }
        }
        __syncthreads();
    }

    // store partials
    int tk0 = tok_s[tokA];
    int tk1 = tok_s[tokA + 8];
    #pragma unroll
    for (int nt = 0; nt < 4; nt++) {
        int n = nb + nt * 8 + 2 * tg;
        if (tk0 >= 0) {
            g_part[sp][tk0][n]     = acc[nt][0];
            g_part[sp][tk0][n + 1] = acc[nt][1];
        }
        if (tk1 >= 0) {
            g_part[sp][tk1][n]     = acc[nt][2];
            g_part[sp][tk1][n + 1] = acc[nt][3];
        }
    }
}

// ---------------- ffn stage 2: reduce + b1 + relu + w2 + log_softmax --------
__global__ __launch_bounds__(256)
void ffn2_kernel(const float* __restrict__ b1, const float* __restrict__ w2,
                 const float* __restrict__ b2, float* __restrict__ out) {
    __shared__ float he_s[32 * 129];
    __shared__ int tok_s[32];
    const int e = blockIdx.y, mt = blockIdx.x, t = threadIdx.x;
    const int count = g_cnt[e];
    if (mt * 32 >= count) return;
    if (t < 32) {
        int r = mt * 32 + t;
        tok_s[t] = (r < count) ? g_bucket[e * B_TOK + r] : -1;
    }
    __syncthreads();
    const float* b1e = b1 + e * H_DIM;
    for (int i4 = t; i4 < 1024; i4 += 256) {
        int row = i4 >> 5, c4 = (i4 & 31) << 2;
        int tok = tok_s[row];
        float sx = 0.f, sy = 0.f, sz = 0.f, sw = 0.f;
        if (tok >= 0)
            #pragma unroll
            for (int sp = 0; sp < SPLITS; sp++) {
                float4 p = *(const float4*)&g_part[sp][tok][c4];
                sx += p.x; sy += p.y; sz += p.z; sw += p.w;
            }
        he_s[row * 129 + c4 + 0] = fmaxf(sx + b1e[c4 + 0], 0.f);
        he_s[row * 129 + c4 + 1] = fmaxf(sy + b1e[c4 + 1], 0.f);
        he_s[row * 129 + c4 + 2] = fmaxf(sz + b1e[c4 + 2], 0.f);
        he_s[row * 129 + c4 + 3] = fmaxf(sw + b1e[c4 + 3], 0.f);
    }
    __syncthreads();
    if (t < 32) {
        int r = mt * 32 + t;
        if (r < count) {
            int tok = tok_s[t];
            const float* w2e = w2 + e * (H_DIM * O_DIM);
            const float* b2e = b2 + e * O_DIM;
            float o[O_DIM];
            #pragma unroll
            for (int oo = 0; oo < O_DIM; oo++) o[oo] = b2e[oo];
            const float* hh = he_s + t * 129;
            for (int hi = 0; hi < H_DIM; hi++) {
                float hv = hh[hi];
                const float* wr = w2e + hi * O_DIM;
                #pragma unroll
                for (int oo = 0; oo < O_DIM; oo++)
                    o[oo] = fmaf(hv, wr[oo], o[oo]);
            }
            float sc = g_scale[tok];
            float m = -1e30f;
            #pragma unroll
            for (int oo = 0; oo < O_DIM; oo++) { o[oo] *= sc; m = fmaxf(m, o[oo]); }
            float s = 0.f;
            #pragma unroll
            for (int oo = 0; oo < O_DIM; oo++) s += expf(o[oo] - m);
            float lse = m + logf(s);
            #pragma unroll
            for (int oo = 0; oo < O_DIM; oo++)
                out[tok * O_DIM + oo] = o[oo] - lse;
        }
    }
}

// ---------------- launch -----------------------------------------------------
extern "C" void kernel_launch(void* const* d_in, const int* in_sizes, int n_in,
                              void* d_out, int out_size) {
    const float* x   = (const float*)d_in[0];
    const float* c1w = (const float*)d_in[1];
    const float* c1b = (const float*)d_in[2];
    const float* c2w = (const float*)d_in[3];
    const float* c2b = (const float*)d_in[4];
    const float* gw  = (const float*)d_in[5];
    const float* w1  = (const float*)d_in[6];
    const float* b1  = (const float*)d_in[7];
    const float* w2  = (const float*)d_in[8];
    const float* b2  = (const float*)d_in[9];
    float* out = (float*)d_out;

    cudaFuncSetAttribute(conv_kernel, cudaFuncAttributeMaxDynamicSharedMemorySize,
                         CONV_SMEM_FLOATS * (int)sizeof(float));
    reset_kernel<<<1, 32>>>();
    w1pack_kernel<<<18432, 256>>>(w1);
    conv_kernel<<<B_TOK, CONV_THREADS, CONV_SMEM_FLOATS * sizeof(float)>>>(
        x, c1w, c1b, c2w, c2b);
    gate_kernel<<<B_TOK, 256>>>(gw);
    ffn1_kernel<<<dim3(128, E_EXP, SPLITS), 256>>>();
    ffn2_kernel<<<dim3(128, E_EXP), 256>>>(b1, w2, b2, out);
}

// round 12
// speedup vs baseline: 1.2756x; 1.1390x over previous
#include <cuda_runtime.h>
#include <cuda_fp16.h>
#include <math.h>

#define B_TOK 4096
#define D_DIM 9216
#define E_EXP 8
#define H_DIM 128
#define O_DIM 10
#define SPLITS 6
#define KCH (D_DIM / SPLITS)   // 1536
#define GTOK 4

// ---------------- scratch (static device globals) ----------------------------
__device__ unsigned g_hp[(size_t)B_TOK * D_DIM];      // h packed (hi, lo*2048)
__device__ float    g_scale[B_TOK];
__device__ int      g_bucket[E_EXP * B_TOK];
__device__ int      g_cnt[E_EXP];
__device__ float    g_part[SPLITS][B_TOK][H_DIM];
__device__ unsigned g_w1h[(size_t)E_EXP * 4608 * 128]; // w1 fp16 k-pairs

__global__ void reset_kernel() {
    if (threadIdx.x < E_EXP) g_cnt[threadIdx.x] = 0;
}

// ---------------- helpers ----------------------------------------------------
__device__ __forceinline__ void mma_f16(float c[4],
                                        unsigned a0, unsigned a1,
                                        unsigned a2, unsigned a3,
                                        unsigned b0, unsigned b1) {
    asm("mma.sync.aligned.m16n8k16.row.col.f32.f16.f16.f32 "
        "{%0,%1,%2,%3},{%4,%5,%6,%7},{%8,%9},{%0,%1,%2,%3};"
        : "+f"(c[0]), "+f"(c[1]), "+f"(c[2]), "+f"(c[3])
        : "r"(a0), "r"(a1), "r"(a2), "r"(a3), "r"(b0), "r"(b1));
}
__device__ __forceinline__ unsigned h2u(__half2 h) { return *reinterpret_cast<unsigned*>(&h); }
__device__ __forceinline__ __half2 u2h(unsigned u) { return *reinterpret_cast<__half2*>(&u); }
__device__ __forceinline__ float unpackh(unsigned u) {
    return __half2float(__ushort_as_half((unsigned short)(u & 0xffff)))
         + __half2float(__ushort_as_half((unsigned short)(u >> 16))) * 4.8828125e-4f;
}
__device__ __forceinline__ unsigned packh(float v) {
    __half hi = __float2half_rn(v);
    __half lo = __float2half_rn((v - __half2float(hi)) * 2048.f);
    return ((unsigned)__half_as_ushort(lo) << 16) | (unsigned)__half_as_ushort(hi);
}

// ---------------- w1 -> fp16 k-pair pack -------------------------------------
__global__ __launch_bounds__(256)
void w1pack_kernel(const float* __restrict__ w1) {
    size_t idx = (size_t)blockIdx.x * 256 + threadIdx.x;
    int n   = (int)(idx & 127);
    int row = (int)(idx >> 7);
    int e   = row / 4608;
    int kp  = row - e * 4608;
    const float* we = w1 + (size_t)e * D_DIM * H_DIM;
    float w0 = we[(size_t)(2 * kp) * 128 + n];
    float w1v = we[(size_t)(2 * kp + 1) * 128 + n];
    g_w1h[idx] = h2u(__floats2half2_rn(w0, w1v));
}

// ---------------- fused conv1 -> conv2(fp16 3-term mma) -> maxpool -----------
#define CONV_THREADS 576
#define NKS 18
#define OFF_IN   0
#define OFF_C1W  784
#define OFF_C1B  1072
#define OFF_C2B  1104
#define OFF_COFF 1168
#define OFF_C1   1456
#define OFF_BF   (OFF_C1 + 21632)
#define BF_U2    (3 * 8 * NKS * 32)
#define CONV_SMEM_FLOATS (OFF_BF + BF_U2 * 2)

__global__ __launch_bounds__(CONV_THREADS, 1)
void conv_kernel(const float* __restrict__ x,
                 const float* __restrict__ c1w, const float* __restrict__ c1b,
                 const float* __restrict__ c2w, const float* __restrict__ c2b) {
    extern __shared__ float sm[];
    float*    s_in   = sm + OFF_IN;
    float*    s_c1w  = sm + OFF_C1W;
    float*    s_c1b  = sm + OFF_C1B;
    float*    s_c2b  = sm + OFF_C2B;
    int*      s_coff = (int*)(sm + OFF_COFF);
    float*    s_c1   = sm + OFF_C1;
    unsigned* s_c1p  = (unsigned*)(sm + OFF_C1);
    uint2*    s_Bf   = (uint2*)(sm + OFF_BF);

    const int b = blockIdx.x;
    const int t = threadIdx.x;

    const float* xin = x + b * 784;
    for (int i = t; i < 784; i += CONV_THREADS) s_in[i] = xin[i];
    for (int i = t; i < 288; i += CONV_THREADS) s_c1w[i] = c1w[i];
    if (t < 32) s_c1b[t] = c1b[t];
    if (t >= 64 && t < 128) s_c2b[t - 64] = c2b[t - 64];
    if (t >= 128 && t < 416) {
        int k = t - 128;
        int ic = k / 9, kk = k - ic * 9;
        s_coff[k] = ic * 676 + (kk / 3) * 26 + (kk % 3);
    }
    for (int i = t; i < 18432; i += CONV_THREADS) s_c1[i] = c2w[i];
    __syncthreads();

    for (int i = t; i < 8 * NKS * 32; i += CONV_THREADS) {
        int lane = i & 31;
        int rest = i >> 5;
        int ks = rest % NKS;
        int nt = rest / NKS;
        int tg = lane & 3, g = lane >> 2;
        int n = nt * 8 + g;
        int k0 = ks * 16 + 2 * tg;
        const float* wr = s_c1 + n * 288;
        float w0 = wr[k0],     w1 = wr[k0 + 1];
        float w8 = wr[k0 + 8], w9 = wr[k0 + 9];
        __half2 h0 = __floats2half2_rn(w0, w1);
        __half2 h1 = __floats2half2_rn(w8, w9);
        float2 r0 = __half22float2(h0);
        float2 r1 = __half22float2(h1);
        __half2 l0 = __floats2half2_rn((w0 - r0.x) * 64.f, (w1 - r0.y) * 64.f);
        __half2 l1 = __floats2half2_rn((w8 - r1.x) * 64.f, (w9 - r1.y) * 64.f);
        __half2 s0 = __floats2half2_rn(w0 * 0.015625f, w1 * 0.015625f);
        __half2 s1 = __floats2half2_rn(w8 * 0.015625f, w9 * 0.015625f);
        int slot = (nt * NKS + ks) * 32 + lane;
        s_Bf[slot]                 = make_uint2(h2u(h0), h2u(h1));
        s_Bf[slot + 8 * NKS * 32]  = make_uint2(h2u(s0), h2u(s1));
        s_Bf[slot + 16 * NKS * 32] = make_uint2(h2u(l0), h2u(l1));
    }
    __syncthreads();

    for (int i = t; i < 21632; i += CONV_THREADS) {
        int c  = i / 676;
        int p  = i - c * 676;
        int y  = p / 26;
        int xx = p - y * 26;
        const float* wv = s_c1w + c * 9;
        const float* ip = s_in + y * 28 + xx;
        float acc = s_c1b[c];
        #pragma unroll
        for (int ky = 0; ky < 3; ky++)
            #pragma unroll
            for (int kx = 0; kx < 3; kx++)
                acc = fmaf(ip[ky * 28 + kx], wv[ky * 3 + kx], acc);
        s_c1p[i] = packh(fmaxf(acc, 0.f));
    }
    __syncthreads();

    const int lane = t & 31;
    const int wid  = t >> 5;
    const int g    = lane >> 2;
    const int tg   = lane & 3;
    unsigned* hbp = g_hp + (size_t)b * D_DIM;
    const __half2 k5 = __floats2half2_rn(0.03125f, 0.03125f);
    const __half2 k6 = __floats2half2_rn(0.015625f, 0.015625f);

    #pragma unroll
    for (int ti = 0; ti < 2; ti++) {
        const int tt = wid * 2 + ti;
        const int q  = tt * 4 + (g & 3);
        const int p  = (q / 12) * 52 + (q % 12) * 2 + (g >> 2);
        const int p26 = p + 26;

        float acc[8][4];
        #pragma unroll
        for (int nt = 0; nt < 8; nt++)
            #pragma unroll
            for (int i = 0; i < 4; i++) acc[nt][i] = 0.f;

        for (int ks = 0; ks < NKS; ks++) {
            const int kb = ks * 16 + 2 * tg;
            const int c0 = s_coff[kb],     c1 = s_coff[kb + 1];
            const int c2 = s_coff[kb + 8], c3 = s_coff[kb + 9];
            unsigned u00 = s_c1p[p + c0],   u01 = s_c1p[p + c1];
            unsigned u02 = s_c1p[p + c2],   u03 = s_c1p[p + c3];
            unsigned u10 = s_c1p[p26 + c0], u11 = s_c1p[p26 + c1];
            unsigned u12 = s_c1p[p26 + c2], u13 = s_c1p[p26 + c3];

            unsigned ah0 = __byte_perm(u00, u01, 0x5410);
            unsigned ah1 = __byte_perm(u10, u11, 0x5410);
            unsigned ah2 = __byte_perm(u02, u03, 0x5410);
            unsigned ah3 = __byte_perm(u12, u13, 0x5410);
            unsigned al0 = h2u(__hmul2(u2h(__byte_perm(u00, u01, 0x7632)), k5));
            unsigned al1 = h2u(__hmul2(u2h(__byte_perm(u10, u11, 0x7632)), k5));
            unsigned al2 = h2u(__hmul2(u2h(__byte_perm(u02, u03, 0x7632)), k5));
            unsigned al3 = h2u(__hmul2(u2h(__byte_perm(u12, u13, 0x7632)), k5));
            unsigned us0 = h2u(__hmul2(u2h(ah0), k6));
            unsigned us1 = h2u(__hmul2(u2h(ah1), k6));
            unsigned us2 = h2u(__hmul2(u2h(ah2), k6));
            unsigned us3 = h2u(__hmul2(u2h(ah3), k6));

            const uint2* bp = s_Bf + ks * 32 + lane;
            #pragma unroll
            for (int nt = 0; nt < 8; nt++) {
                uint2 bwh = bp[nt * (NKS * 32)];
                uint2 bws = bp[nt * (NKS * 32) + 8 * NKS * 32];
                uint2 bwl = bp[nt * (NKS * 32) + 16 * NKS * 32];
                mma_f16(acc[nt], ah0, ah1, ah2, ah3, bwh.x, bwh.y);
                mma_f16(acc[nt], al0, al1, al2, al3, bws.x, bws.y);
                mma_f16(acc[nt], us0, us1, us2, us3, bwl.x, bwl.y);
            }
        }

        #pragma unroll
        for (int nt = 0; nt < 8; nt++) {
            float v0 = fmaxf(acc[nt][0], acc[nt][2]);
            float v1 = fmaxf(acc[nt][1], acc[nt][3]);
            v0 = fmaxf(v0, __shfl_xor_sync(0xFFFFFFFFu, v0, 16));
            v1 = fmaxf(v1, __shfl_xor_sync(0xFFFFFFFFu, v1, 16));
            int ch0 = nt * 8 + 2 * tg;
            if ((lane < 16) == (nt < 4)) {
                hbp[ch0 * 144 + q]       = packh(fmaxf(v0 + s_c2b[ch0], 0.f));
                hbp[(ch0 + 1) * 144 + q] = packh(fmaxf(v1 + s_c2b[ch0 + 1], 0.f));
            }
        }
    }
}

// ---------------- top-1 gate: 4 tokens/block, coalesced gate_w ---------------
__global__ __launch_bounds__(256)
void gate_kernel(const float* __restrict__ gate_w) {
    __shared__ float red[32 * 272];           // [j=tok*8+e][t], padded rows
    const int bb = blockIdx.x * GTOK;
    const int t  = threadIdx.x;

    float acc[GTOK][8];
    #pragma unroll
    for (int tk = 0; tk < GTOK; tk++)
        #pragma unroll
        for (int e = 0; e < 8; e++) acc[tk][e] = 0.f;

    #pragma unroll 4
    for (int it = 0; it < 36; it++) {
        int d = it * 256 + t;
        const float4* gp = (const float4*)(gate_w + (size_t)d * 8);
        float4 ga = gp[0], gb = gp[1];
        #pragma unroll
        for (int tk = 0; tk < GTOK; tk++) {
            float hv = unpackh(g_hp[(size_t)(bb + tk) * D_DIM + d]);
            acc[tk][0] = fmaf(hv, ga.x, acc[tk][0]);
            acc[tk][1] = fmaf(hv, ga.y, acc[tk][1]);
            acc[tk][2] = fmaf(hv, ga.z, acc[tk][2]);
            acc[tk][3] = fmaf(hv, ga.w, acc[tk][3]);
            acc[tk][4] = fmaf(hv, gb.x, acc[tk][4]);
            acc[tk][5] = fmaf(hv, gb.y, acc[tk][5]);
            acc[tk][6] = fmaf(hv, gb.z, acc[tk][6]);
            acc[tk][7] = fmaf(hv, gb.w, acc[tk][7]);
        }
    }

    #pragma unroll
    for (int tk = 0; tk < GTOK; tk++)
        #pragma unroll
        for (int e = 0; e < 8; e++)
            red[(tk * 8 + e) * 272 + t] = acc[tk][e];
    __syncthreads();
    #pragma unroll
    for (int s = 128; s >= 1; s >>= 1) {
        if (t < s) {
            #pragma unroll
            for (int j = 0; j < 32; j++)
                red[j * 272 + t] += red[j * 272 + t + s];
        }
        __syncthreads();
    }

    if (t < GTOK) {
        float lg[8];
        #pragma unroll
        for (int e = 0; e < 8; e++) lg[e] = red[(t * 8 + e) * 272];
        float m = lg[0];
        int idx = 0;
        #pragma unroll
        for (int e = 1; e < 8; e++) if (lg[e] > m) { m = lg[e]; idx = e; }
        float s = 0.f;
        #pragma unroll
        for (int e = 0; e < 8; e++) s += expf(lg[e] - m);
        int tok = bb + t;
        g_scale[tok] = 1.f / s;
        int pos = atomicAdd(&g_cnt[idx], 1);
        g_bucket[idx * B_TOK + pos] = tok;
    }
}

// ---------------- ffn stage 1: fp16 2-term tensor GEMM -----------------------
__global__ __launch_bounds__(256)
void ffn1_kernel() {
    __shared__ unsigned A_s[64 * 34];
    __shared__ unsigned B_s[32 * 132];
    __shared__ int tok_s[32];

    const int e = blockIdx.y, mt = blockIdx.x, sp = blockIdx.z, t = threadIdx.x;
    const int count = g_cnt[e];
    if (mt * 32 >= count) return;
    if (t < 32) {
        int r = mt * 32 + t;
        tok_s[t] = (r < count) ? g_bucket[e * B_TOK + r] : -1;
    }
    __syncthreads();

    const int lane = t & 31, w = t >> 5;
    const int g = lane >> 2, tg = lane & 3;
    const int mt2 = w & 1;
    const int nb  = (w >> 1) * 32;
    const int tokA = mt2 * 16 + g;
    const __half2 k11 = __floats2half2_rn(4.8828125e-4f, 4.8828125e-4f);

    float acc[4][4];
    #pragma unroll
    for (int nt = 0; nt < 4; nt++)
        #pragma unroll
        for (int i = 0; i < 4; i++) acc[nt][i] = 0.f;

    const int rowbase = e * 4608 + sp * 768;

    for (int kb = 0; kb < KCH; kb += 64) {
        unsigned uA[8];
        uint4 uB[4];
        #pragma unroll
        for (int v = 0; v < 8; v++) {
            int i = t + 256 * v;
            int ltok = i >> 6, lk = i & 63;
            int tk = tok_s[ltok];
            uA[v] = g_hp[(size_t)(tk >= 0 ? tk : 0) * D_DIM + sp * KCH + kb + lk];
        }
        #pragma unroll
        for (int v = 0; v < 4; v++) {
            int f = t + 256 * v;
            int kp = f >> 5, n4 = (f & 31) * 4;
            uB[v] = *(const uint4*)&g_w1h[(size_t)(rowbase + (kb >> 1) + kp) * 128 + n4];
        }
        __syncthreads();
        #pragma unroll
        for (int v = 0; v < 8; v++) {
            int i = t + 256 * v;
            A_s[(i & 63) * 34 + (i >> 6)] = uA[v];
        }
        #pragma unroll
        for (int v = 0; v < 4; v++) {
            int f = t + 256 * v;
            int kp = f >> 5, n4 = (f & 31) * 4;
            *(uint4*)&B_s[kp * 132 + n4] = uB[v];
        }
        __syncthreads();

        #pragma unroll
        for (int s = 0; s < 4; s++) {
            const int K = s * 16;
            unsigned u00 = A_s[(K + 2 * tg) * 34 + tokA];
            unsigned u01 = A_s[(K + 2 * tg + 1) * 34 + tokA];
            unsigned u02 = A_s[(K + 2 * tg + 8) * 34 + tokA];
            unsigned u03 = A_s[(K + 2 * tg + 9) * 34 + tokA];
            unsigned u10 = A_s[(K + 2 * tg) * 34 + tokA + 8];
            unsigned u11 = A_s[(K + 2 * tg + 1) * 34 + tokA + 8];
            unsigned u12 = A_s[(K + 2 * tg + 8) * 34 + tokA + 8];
            unsigned u13 = A_s[(K + 2 * tg + 9) * 34 + tokA + 8];
            unsigned ah0 = __byte_perm(u00, u01, 0x5410);
            unsigned ah1 = __byte_perm(u10, u11, 0x5410);
            unsigned ah2 = __byte_perm(u02, u03, 0x5410);
            unsigned ah3 = __byte_perm(u12, u13, 0x5410);
            unsigned al0 = h2u(__hmul2(u2h(__byte_perm(u00, u01, 0x7632)), k11));
            unsigned al1 = h2u(__hmul2(u2h(__byte_perm(u10, u11, 0x7632)), k11));
            unsigned al2 = h2u(__hmul2(u2h(__byte_perm(u02, u03, 0x7632)), k11));
            unsigned al3 = h2u(__hmul2(u2h(__byte_perm(u12, u13, 0x7632)), k11));
            const int kq = s * 8;
            #pragma unroll
            for (int nt = 0; nt < 4; nt++) {
                int n = nb + nt * 8 + g;
                unsigned b0 = B_s[(kq + tg) * 132 + n];
                unsigned b1 = B_s[(kq + tg + 4) * 132 + n];
                mma_f16(acc[nt], ah0, ah1, ah2, ah3, b0, b1);
                mma_f16(acc[nt], al0, al1, al2, al3, b0, b1);
            }
        }
        __syncthreads();
    }

    int tk0 = tok_s[tokA];
    int tk1 = tok_s[tokA + 8];
    #pragma unroll
    for (int nt = 0; nt < 4; nt++) {
        int n = nb + nt * 8 + 2 * tg;
        if (tk0 >= 0) {
            g_part[sp][tk0][n]     = acc[nt][0];
            g_part[sp][tk0][n + 1] = acc[nt][1];
        }
        if (tk1 >= 0) {
            g_part[sp][tk1][n]     = acc[nt][2];
            g_part[sp][tk1][n + 1] = acc[nt][3];
        }
    }
}

// ---------------- ffn stage 2: reduce + b1 + relu + w2 + log_softmax --------
__global__ __launch_bounds__(256)
void ffn2_kernel(const float* __restrict__ b1, const float* __restrict__ w2,
                 const float* __restrict__ b2, float* __restrict__ out) {
    __shared__ float he_s[32 * 129];
    __shared__ int tok_s[32];
    const int e = blockIdx.y, mt = blockIdx.x, t = threadIdx.x;
    const int count = g_cnt[e];
    if (mt * 32 >= count) return;
    if (t < 32) {
        int r = mt * 32 + t;
        tok_s[t] = (r < count) ? g_bucket[e * B_TOK + r] : -1;
    }
    __syncthreads();
    const float* b1e = b1 + e * H_DIM;
    for (int i4 = t; i4 < 1024; i4 += 256) {
        int row = i4 >> 5, c4 = (i4 & 31) << 2;
        int tok = tok_s[row];
        float sx = 0.f, sy = 0.f, sz = 0.f, sw = 0.f;
        if (tok >= 0)
            #pragma unroll
            for (int sp = 0; sp < SPLITS; sp++) {
                float4 p = *(const float4*)&g_part[sp][tok][c4];
                sx += p.x; sy += p.y; sz += p.z; sw += p.w;
            }
        he_s[row * 129 + c4 + 0] = fmaxf(sx + b1e[c4 + 0], 0.f);
        he_s[row * 129 + c4 + 1] = fmaxf(sy + b1e[c4 + 1], 0.f);
        he_s[row * 129 + c4 + 2] = fmaxf(sz + b1e[c4 + 2], 0.f);
        he_s[row * 129 + c4 + 3] = fmaxf(sw + b1e[c4 + 3], 0.f);
    }
    __syncthreads();
    if (t < 32) {
        int r = mt * 32 + t;
        if (r < count) {
            int tok = tok_s[t];
            const float* w2e = w2 + e * (H_DIM * O_DIM);
            const float* b2e = b2 + e * O_DIM;
            float o[O_DIM];
            #pragma unroll
            for (int oo = 0; oo < O_DIM; oo++) o[oo] = b2e[oo];
            const float* hh = he_s + t * 129;
            for (int hi = 0; hi < H_DIM; hi++) {
                float hv = hh[hi];
                const float* wr = w2e + hi * O_DIM;
                #pragma unroll
                for (int oo = 0; oo < O_DIM; oo++)
                    o[oo] = fmaf(hv, wr[oo], o[oo]);
            }
            float sc = g_scale[tok];
            float m = -1e30f;
            #pragma unroll
            for (int oo = 0; oo < O_DIM; oo++) { o[oo] *= sc; m = fmaxf(m, o[oo]); }
            float s = 0.f;
            #pragma unroll
            for (int oo = 0; oo < O_DIM; oo++) s += expf(o[oo] - m);
            float lse = m + logf(s);
            #pragma unroll
            for (int oo = 0; oo < O_DIM; oo++)
                out[tok * O_DIM + oo] = o[oo] - lse;
        }
    }
}

// ---------------- launch -----------------------------------------------------
extern "C" void kernel_launch(void* const* d_in, const int* in_sizes, int n_in,
                              void* d_out, int out_size) {
    const float* x   = (const float*)d_in[0];
    const float* c1w = (const float*)d_in[1];
    const float* c1b = (const float*)d_in[2];
    const float* c2w = (const float*)d_in[3];
    const float* c2b = (const float*)d_in[4];
    const float* gw  = (const float*)d_in[5];
    const float* w1  = (const float*)d_in[6];
    const float* b1  = (const float*)d_in[7];
    const float* w2  = (const float*)d_in[8];
    const float* b2  = (const float*)d_in[9];
    float* out = (float*)d_out;

    cudaFuncSetAttribute(conv_kernel, cudaFuncAttributeMaxDynamicSharedMemorySize,
                         CONV_SMEM_FLOATS * (int)sizeof(float));
    reset_kernel<<<1, 32>>>();
    w1pack_kernel<<<18432, 256>>>(w1);
    conv_kernel<<<B_TOK, CONV_THREADS, CONV_SMEM_FLOATS * sizeof(float)>>>(
        x, c1w, c1b, c2w, c2b);
    gate_kernel<<<B_TOK / GTOK, 256>>>(gw);
    ffn1_kernel<<<dim3(128, E_EXP, SPLITS), 256>>>();
    ffn2_kernel<<<dim3(128, E_EXP), 256>>>(b1, w2, b2, out);
}